// round 11
// baseline (speedup 1.0000x reference)
#include <cuda_runtime.h>
#include <math.h>

#define NP 256        // particles
#define ND 3
#define NR 64         // rbfs
#define NH 128        // hidden
#define NB 16         // batch
#define FEPS 1e-6f

#define K_TAB 256
#define D_MAX 12.0f
#define E_PER_BLK 2   // table entries per build block (plus 1-entry halo each side)

__device__ float4 coef_tab[K_TAB];   // u-form quadratic coeffs of -2*g(d)

__device__ __forceinline__ unsigned long long pack2(float lo, float hi) {
    unsigned long long p;
    asm("mov.b64 %0, {%1, %2};" : "=l"(p) : "f"(lo), "f"(hi));
    return p;
}

__device__ __forceinline__ float fast_tanh(float a) {
    float e = __expf(2.0f * a);
    return 1.0f - __fdividef(2.0f, e + 1.0f);
}

// ---------------------------------------------------------------------------
// Kernel 1: tabulate -2*g(d), g(d) = d/dd [ W2 . tanh(rbf(d) @ W1 + b1) ],
// and emit u-form quadratic interpolation coefficients directly.
// Grid 128, 128 threads = 1 hidden unit each; 2 entries + 1-entry halo/side.
// ---------------------------------------------------------------------------
__global__ __launch_bounds__(128) void build_tab_kernel(
    const float* __restrict__ mus, const float* __restrict__ log_gammas,
    const float* __restrict__ W1, const float* __restrict__ b1,
    const float* __restrict__ W2)
{
    __shared__ unsigned long long rbf_pk[E_PER_BLK + 2][NR];  // 2 KB
    __shared__ float partial[E_PER_BLK + 2][4];

    const int tid = threadIdx.x;
    const int e0  = blockIdx.x * E_PER_BLK;
    const float step = D_MAX / (float)(K_TAB - 1);

#pragma unroll
    for (int it = 0; it < 2; it++) {
        int idx = it * 128 + tid;
        int el = idx >> 6, r = idx & 63;
        int e  = min(max(e0 - 1 + el, 0), K_TAB - 1);
        float d   = (float)e * step;
        float gma = __expf(log_gammas[r]);
        float dm  = d - mus[r];
        float ex  = __expf(-gma * dm * dm);
        rbf_pk[el][r] = pack2(ex, -2.0f * gma * dm * ex);
    }

    float w[NR];
#pragma unroll
    for (int r = 0; r < NR; r++) w[r] = W1[r * NH + tid];
    const float b1h = b1[tid];
    const float W2h = W2[tid];
    __syncthreads();

    const int warp = tid >> 5;
#pragma unroll
    for (int el = 0; el < E_PER_BLK + 2; el++) {
        unsigned long long acc0 = pack2(b1h, 0.0f);   // {a, sb}
        unsigned long long acc1 = pack2(0.0f, 0.0f);
        unsigned long long acc2 = pack2(0.0f, 0.0f);
        unsigned long long acc3 = pack2(0.0f, 0.0f);
        const unsigned long long* rb = rbf_pk[el];
#pragma unroll
        for (int r = 0; r < NR; r += 4) {
            unsigned long long w0, w1, w2, w3;
            asm("mov.b64 %0, {%1, %1};" : "=l"(w0) : "f"(w[r + 0]));
            asm("mov.b64 %0, {%1, %1};" : "=l"(w1) : "f"(w[r + 1]));
            asm("mov.b64 %0, {%1, %1};" : "=l"(w2) : "f"(w[r + 2]));
            asm("mov.b64 %0, {%1, %1};" : "=l"(w3) : "f"(w[r + 3]));
            asm("fma.rn.f32x2 %0, %1, %2, %0;" : "+l"(acc0) : "l"(rb[r + 0]), "l"(w0));
            asm("fma.rn.f32x2 %0, %1, %2, %0;" : "+l"(acc1) : "l"(rb[r + 1]), "l"(w1));
            asm("fma.rn.f32x2 %0, %1, %2, %0;" : "+l"(acc2) : "l"(rb[r + 2]), "l"(w2));
            asm("fma.rn.f32x2 %0, %1, %2, %0;" : "+l"(acc3) : "l"(rb[r + 3]), "l"(w3));
        }
        float a0, s0, a1, s1, a2, s2, a3, s3;
        asm("mov.b64 {%0, %1}, %2;" : "=f"(a0), "=f"(s0) : "l"(acc0));
        asm("mov.b64 {%0, %1}, %2;" : "=f"(a1), "=f"(s1) : "l"(acc1));
        asm("mov.b64 {%0, %1}, %2;" : "=f"(a2), "=f"(s2) : "l"(acc2));
        asm("mov.b64 {%0, %1}, %2;" : "=f"(a3), "=f"(s3) : "l"(acc3));
        float a  = (a0 + a1) + (a2 + a3);
        float sb = (s0 + s1) + (s2 + s3);
        float t  = fast_tanh(a);
        float contrib = W2h * (1.0f - t * t) * sb;
#pragma unroll
        for (int off = 16; off > 0; off >>= 1)
            contrib += __shfl_xor_sync(0xFFFFFFFFu, contrib, off);
        if ((tid & 31) == 0) partial[el][warp] = contrib;
    }
    __syncthreads();

    if (tid < E_PER_BLK) {
        float T[E_PER_BLK + 2];
#pragma unroll
        for (int el = 0; el < E_PER_BLK + 2; el++)
            T[el] = -2.0f * (partial[el][0] + partial[el][1]
                           + partial[el][2] + partial[el][3]);
        const int k = e0 + tid;
        float gm = T[tid], g0 = T[tid + 1], gp = T[tid + 2];
        float c1 = 0.5f * (gp - gm);
        float c2 = 0.5f * (gp - 2.0f * g0 + gm);
        float fk = (float)k;
        float c1u = c1 - 2.0f * c2 * fk;
        float c0u = g0 - fk * (c1 - c2 * fk);
        coef_tab[k] = make_float4(c0u, c1u, c2, 0.0f);
    }
}

// ---------------------------------------------------------------------------
// Kernel 2: forces, phase-batched for ILP. Grid (NP/16, NB) = 256 blocks x
// 256 threads: 16 i's per block, 16 lanes per i (16 j each, in 2 halves of 8).
// Each half runs as explicit dataflow phases over 8-element register arrays:
//   24 independent LDS -> 8 independent d2 FMA trees -> 8 pipelined RSQ ->
//   8 independent coef LDS.128 + interp + accumulate.
// This forces ptxas to hold ~8 iterations in flight (regs ~80-110) instead of
// the 32-reg serial schedule that stalled R8/R10.
// CoM mean subtraction skipped (pair antisymmetry: mean is rounding noise).
// ---------------------------------------------------------------------------
__global__ __launch_bounds__(256) void force_kernel(
    const float* __restrict__ xs, float* __restrict__ out)
{
    __shared__ float px[NP], py[NP], pz[NP];
    __shared__ float4 coef[K_TAB];

    const int b   = blockIdx.y;
    const int tid = threadIdx.x;

    const float* xb = xs + (size_t)b * NP * ND;
#pragma unroll
    for (int it = 0; it < 3; it++) {
        int idx = it * 256 + tid;
        float v = __ldg(xb + idx);
        int j = idx / 3, c = idx - j * 3;
        if (c == 0) px[j] = v; else if (c == 1) py[j] = v; else pz[j] = v;
    }
    coef[tid] = __ldg(&coef_tab[tid]);   // coalesced LDG.128 -> STS.128
    __syncthreads();

    const int i = blockIdx.x * 16 + (tid >> 4);
    const int q = tid & 15;
    const float xi = px[i], yi = py[i], zi = pz[i];
    const float inv_step = (float)(K_TAB - 1) / D_MAX;

    float ax = 0.f, ay = 0.f, az = 0.f;
#pragma unroll
    for (int half = 0; half < 2; half++) {
        float rx[8], ry[8], rz[8], d2[8], invd[8], uu[8];
        // Phase A: 24 independent shared loads
#pragma unroll
        for (int m = 0; m < 8; m++) {
            int j = (half * 8 + m) * 16 + q;
            rx[m] = xi - px[j];
            ry[m] = yi - py[j];
            rz[m] = zi - pz[j];
        }
        // Phase B: 8 independent FMA trees
#pragma unroll
        for (int m = 0; m < 8; m++)
            d2[m] = fmaf(rx[m], rx[m], fmaf(ry[m], ry[m], fmaf(rz[m], rz[m], FEPS)));
        // Phase C: 8 pipelined MUFU.RSQ
#pragma unroll
        for (int m = 0; m < 8; m++)
            invd[m] = rsqrtf(d2[m]);
        // Phase D: index math (independent)
#pragma unroll
        for (int m = 0; m < 8; m++)
            uu[m] = fminf(d2[m] * invd[m] * inv_step, (float)(K_TAB - 2));
        // Phase E: 8 independent coef fetches + interp + accumulate
#pragma unroll
        for (int m = 0; m < 8; m++) {
            int k = __float2int_rd(uu[m]);
            float4 c = coef[k];
            float g  = fmaf(uu[m], fmaf(uu[m], c.z, c.y), c.x);
            float s  = g * invd[m];          // j==i: r=0 -> contributes 0
            ax = fmaf(s, rx[m], ax);
            ay = fmaf(s, ry[m], ay);
            az = fmaf(s, rz[m], az);
        }
    }
    // combine the 16 j-partitions (consecutive lanes share i)
#pragma unroll
    for (int off = 1; off < 16; off <<= 1) {
        ax += __shfl_xor_sync(0xFFFFFFFFu, ax, off);
        ay += __shfl_xor_sync(0xFFFFFFFFu, ay, off);
        az += __shfl_xor_sync(0xFFFFFFFFu, az, off);
    }

    if (q == 0) {
        float* o = out + ((size_t)b * NP + i) * 3;
        o[0] = ax;    // -2 factor baked into coef_tab
        o[1] = ay;
        o[2] = az;
    }
}

// ---------------------------------------------------------------------------
// Inputs (metadata order): t(1), xs(12288), mus(64), log_gammas(64),
//                          W1(8192), b1(128), W2(128), b2(1)
// Output: float32 (16, 256, 3)
// ---------------------------------------------------------------------------
extern "C" void kernel_launch(void* const* d_in, const int* in_sizes, int n_in,
                              void* d_out, int out_size)
{
    const float* xs  = (const float*)d_in[1];
    const float* mus = (const float*)d_in[2];
    const float* lg  = (const float*)d_in[3];
    const float* W1  = (const float*)d_in[4];
    const float* b1  = (const float*)d_in[5];
    const float* W2  = (const float*)d_in[6];
    float* out = (float*)d_out;

    build_tab_kernel<<<K_TAB / E_PER_BLK, 128>>>(mus, lg, W1, b1, W2);
    force_kernel<<<dim3(NP / 16, NB), 256>>>(xs, out);
}

// round 13
// speedup vs baseline: 1.0554x; 1.0554x over previous
#include <cuda_runtime.h>
#include <math.h>

#define NP 256        // particles
#define ND 3
#define NR 64         // rbfs
#define NH 128        // hidden
#define NB 16         // batch
#define FEPS 1e-6f

#define K_TAB 256
#define D_MAX 12.0f
#define E_PER_BLK 2   // table entries per build block (plus 1-entry halo each side)

__device__ float4 coef_tab[K_TAB];   // u-form quadratic coeffs of -2*g(d)

__device__ __forceinline__ unsigned long long pack2(float lo, float hi) {
    unsigned long long p;
    asm("mov.b64 %0, {%1, %2};" : "=l"(p) : "f"(lo), "f"(hi));
    return p;
}

__device__ __forceinline__ float fast_tanh(float a) {
    float e = __expf(2.0f * a);
    return 1.0f - __fdividef(2.0f, e + 1.0f);
}

// ---------------------------------------------------------------------------
// Kernel 1: tabulate -2*g(d), g(d) = d/dd [ W2 . tanh(rbf(d) @ W1 + b1) ],
// emit u-form quadratic interpolation coefficients directly.
// Grid 128, 128 threads = 1 hidden unit each; 2 entries + 1-entry halo/side.
// ---------------------------------------------------------------------------
__global__ __launch_bounds__(128) void build_tab_kernel(
    const float* __restrict__ mus, const float* __restrict__ log_gammas,
    const float* __restrict__ W1, const float* __restrict__ b1,
    const float* __restrict__ W2)
{
    __shared__ unsigned long long rbf_pk[E_PER_BLK + 2][NR];  // 2 KB
    __shared__ float partial[E_PER_BLK + 2][4];

    const int tid = threadIdx.x;
    const int e0  = blockIdx.x * E_PER_BLK;
    const float step = D_MAX / (float)(K_TAB - 1);

#pragma unroll
    for (int it = 0; it < 2; it++) {
        int idx = it * 128 + tid;
        int el = idx >> 6, r = idx & 63;
        int e  = min(max(e0 - 1 + el, 0), K_TAB - 1);
        float d   = (float)e * step;
        float gma = __expf(log_gammas[r]);
        float dm  = d - mus[r];
        float ex  = __expf(-gma * dm * dm);
        rbf_pk[el][r] = pack2(ex, -2.0f * gma * dm * ex);
    }

    float w[NR];
#pragma unroll
    for (int r = 0; r < NR; r++) w[r] = W1[r * NH + tid];
    const float b1h = b1[tid];
    const float W2h = W2[tid];
    __syncthreads();

    const int warp = tid >> 5;
#pragma unroll
    for (int el = 0; el < E_PER_BLK + 2; el++) {
        unsigned long long acc0 = pack2(b1h, 0.0f);   // {a, sb}
        unsigned long long acc1 = pack2(0.0f, 0.0f);
        unsigned long long acc2 = pack2(0.0f, 0.0f);
        unsigned long long acc3 = pack2(0.0f, 0.0f);
        const unsigned long long* rb = rbf_pk[el];
#pragma unroll
        for (int r = 0; r < NR; r += 4) {
            unsigned long long w0, w1, w2, w3;
            asm("mov.b64 %0, {%1, %1};" : "=l"(w0) : "f"(w[r + 0]));
            asm("mov.b64 %0, {%1, %1};" : "=l"(w1) : "f"(w[r + 1]));
            asm("mov.b64 %0, {%1, %1};" : "=l"(w2) : "f"(w[r + 2]));
            asm("mov.b64 %0, {%1, %1};" : "=l"(w3) : "f"(w[r + 3]));
            asm("fma.rn.f32x2 %0, %1, %2, %0;" : "+l"(acc0) : "l"(rb[r + 0]), "l"(w0));
            asm("fma.rn.f32x2 %0, %1, %2, %0;" : "+l"(acc1) : "l"(rb[r + 1]), "l"(w1));
            asm("fma.rn.f32x2 %0, %1, %2, %0;" : "+l"(acc2) : "l"(rb[r + 2]), "l"(w2));
            asm("fma.rn.f32x2 %0, %1, %2, %0;" : "+l"(acc3) : "l"(rb[r + 3]), "l"(w3));
        }
        float a0, s0, a1, s1, a2, s2, a3, s3;
        asm("mov.b64 {%0, %1}, %2;" : "=f"(a0), "=f"(s0) : "l"(acc0));
        asm("mov.b64 {%0, %1}, %2;" : "=f"(a1), "=f"(s1) : "l"(acc1));
        asm("mov.b64 {%0, %1}, %2;" : "=f"(a2), "=f"(s2) : "l"(acc2));
        asm("mov.b64 {%0, %1}, %2;" : "=f"(a3), "=f"(s3) : "l"(acc3));
        float a  = (a0 + a1) + (a2 + a3);
        float sb = (s0 + s1) + (s2 + s3);
        float t  = fast_tanh(a);
        float contrib = W2h * (1.0f - t * t) * sb;
#pragma unroll
        for (int off = 16; off > 0; off >>= 1)
            contrib += __shfl_xor_sync(0xFFFFFFFFu, contrib, off);
        if ((tid & 31) == 0) partial[el][warp] = contrib;
    }
    __syncthreads();

    if (tid < E_PER_BLK) {
        float T[E_PER_BLK + 2];
#pragma unroll
        for (int el = 0; el < E_PER_BLK + 2; el++)
            T[el] = -2.0f * (partial[el][0] + partial[el][1]
                           + partial[el][2] + partial[el][3]);
        const int k = e0 + tid;
        float gm = T[tid], g0 = T[tid + 1], gp = T[tid + 2];
        float c1 = 0.5f * (gp - gm);
        float c2 = 0.5f * (gp - 2.0f * g0 + gm);
        float fk = (float)k;
        float c1u = c1 - 2.0f * c2 * fk;
        float c0u = g0 - fk * (c1 - c2 * fk);
        coef_tab[k] = make_float4(c0u, c1u, c2, 0.0f);
    }
}

// Empty asm: forces v to be materialized in a register HERE and blocks
// ptxas from sinking/fusing the producing phase into later consumers.
#define PIN(v) asm volatile("" : "+f"(v))

// ---------------------------------------------------------------------------
// Kernel 2: forces with COMPILER-ENFORCED 16-way ILP.
// Grid (NP/16, NB) = 256 blocks x 256 threads: 16 i's per block, 16 lanes
// per i (16 j each). Positions packed float4 in smem (1 LDS.128 per pair).
// Dataflow phases over 16-element register arrays, each phase sealed with
// liveness pins so ptxas cannot re-serialize (R11 failure mode: regs=32).
// CoM mean subtraction skipped (pair antisymmetry: mean is rounding noise).
// ---------------------------------------------------------------------------
__global__ __launch_bounds__(256) void force_kernel(
    const float* __restrict__ xs, float* __restrict__ out)
{
    __shared__ float4 pos[NP];     // 4 KB (x, y, z, 0)
    __shared__ float4 coef[K_TAB]; // 4 KB

    const int b   = blockIdx.y;
    const int tid = threadIdx.x;

    const float* xb = xs + (size_t)b * NP * ND;
    {
        int j = tid;   // one particle per thread
        pos[j] = make_float4(__ldg(xb + j * 3 + 0),
                             __ldg(xb + j * 3 + 1),
                             __ldg(xb + j * 3 + 2), 0.0f);
        coef[tid] = __ldg(&coef_tab[tid]);
    }
    __syncthreads();

    const int i = blockIdx.x * 16 + (tid >> 4);
    const int q = tid & 15;
    const float4 pi = pos[i];
    const float xi = pi.x, yi = pi.y, zi = pi.z;
    const float inv_step = (float)(K_TAB - 1) / D_MAX;

    float rx[16], ry[16], rz[16], d2[16], invd[16], uu[16];

    // Phase A: 16 independent LDS.128 position fetches
#pragma unroll
    for (int m = 0; m < 16; m++) {
        float4 pj = pos[m * 16 + q];
        rx[m] = xi - pj.x;
        ry[m] = yi - pj.y;
        rz[m] = zi - pj.z;
    }
#pragma unroll
    for (int m = 0; m < 16; m++) { PIN(rx[m]); PIN(ry[m]); PIN(rz[m]); }

    // Phase B: 16 independent d2 FMA trees
#pragma unroll
    for (int m = 0; m < 16; m++)
        d2[m] = fmaf(rx[m], rx[m], fmaf(ry[m], ry[m], fmaf(rz[m], rz[m], FEPS)));
#pragma unroll
    for (int m = 0; m < 16; m++) PIN(d2[m]);

    // Phase C: 16 pipelined MUFU.RSQ
#pragma unroll
    for (int m = 0; m < 16; m++)
        invd[m] = rsqrtf(d2[m]);
#pragma unroll
    for (int m = 0; m < 16; m++) PIN(invd[m]);

    // Phase D: table coordinate
#pragma unroll
    for (int m = 0; m < 16; m++)
        uu[m] = fminf(d2[m] * invd[m] * inv_step, (float)(K_TAB - 2));
#pragma unroll
    for (int m = 0; m < 16; m++) PIN(uu[m]);

    // Phase E: 16 independent coef LDS.128 + interp + accumulate
    float ax = 0.f, ay = 0.f, az = 0.f;
#pragma unroll
    for (int m = 0; m < 16; m++) {
        int k = __float2int_rd(uu[m]);
        float4 c = coef[k];
        float g  = fmaf(uu[m], fmaf(uu[m], c.z, c.y), c.x);
        float s  = g * invd[m];          // j==i: r=0 -> contributes 0
        ax = fmaf(s, rx[m], ax);
        ay = fmaf(s, ry[m], ay);
        az = fmaf(s, rz[m], az);
    }

    // combine the 16 j-partitions (consecutive lanes share i)
#pragma unroll
    for (int off = 1; off < 16; off <<= 1) {
        ax += __shfl_xor_sync(0xFFFFFFFFu, ax, off);
        ay += __shfl_xor_sync(0xFFFFFFFFu, ay, off);
        az += __shfl_xor_sync(0xFFFFFFFFu, az, off);
    }

    if (q == 0) {
        float* o = out + ((size_t)b * NP + i) * 3;
        o[0] = ax;    // -2 factor baked into coef_tab
        o[1] = ay;
        o[2] = az;
    }
}

// ---------------------------------------------------------------------------
// Inputs (metadata order): t(1), xs(12288), mus(64), log_gammas(64),
//                          W1(8192), b1(128), W2(128), b2(1)
// Output: float32 (16, 256, 3)
// ---------------------------------------------------------------------------
extern "C" void kernel_launch(void* const* d_in, const int* in_sizes, int n_in,
                              void* d_out, int out_size)
{
    const float* xs  = (const float*)d_in[1];
    const float* mus = (const float*)d_in[2];
    const float* lg  = (const float*)d_in[3];
    const float* W1  = (const float*)d_in[4];
    const float* b1  = (const float*)d_in[5];
    const float* W2  = (const float*)d_in[6];
    float* out = (float*)d_out;

    build_tab_kernel<<<K_TAB / E_PER_BLK, 128>>>(mus, lg, W1, b1, W2);
    force_kernel<<<dim3(NP / 16, NB), 256>>>(xs, out);
}